// round 11
// baseline (speedup 1.0000x reference)
#include <cuda_runtime.h>
#include <cuda_bf16.h>
#include <cstdint>

#define NDIM   1024
#define NHEADS 16
#define HDIM   64
#define NB     4
#define NL     2048
#define NM     (NB * NL)        // 8192 rows
#define QKV_N  (3 * NDIM)       // 3072

// ---------------------------------------------------------------------------
// Scratch (allocation-free rule: static __device__ globals)
// ---------------------------------------------------------------------------
__device__ __nv_bfloat16 g_xh[(size_t)NM * NDIM];
__device__ __nv_bfloat16 g_xl[(size_t)NM * NDIM];
__device__ __nv_bfloat16 g_wqh[(size_t)QKV_N * NDIM];
__device__ __nv_bfloat16 g_wql[(size_t)QKV_N * NDIM];
__device__ __nv_bfloat16 g_wph[(size_t)NDIM * NDIM];
__device__ __nv_bfloat16 g_wpl[(size_t)NDIM * NDIM];
// q/k/v hi/lo in [B,H,L,64] layout (written by qkv GEMM epilogue)
__device__ __nv_bfloat16 g_qh[(size_t)NB * NHEADS * NL * HDIM];
__device__ __nv_bfloat16 g_ql[(size_t)NB * NHEADS * NL * HDIM];
__device__ __nv_bfloat16 g_kh[(size_t)NB * NHEADS * NL * HDIM];
__device__ __nv_bfloat16 g_kl[(size_t)NB * NHEADS * NL * HDIM];
__device__ __nv_bfloat16 g_vh[(size_t)NB * NHEADS * NL * HDIM];
__device__ __nv_bfloat16 g_vl[(size_t)NB * NHEADS * NL * HDIM];
// attention output hi/lo [8192,1024] (input to proj GEMM)
__device__ __nv_bfloat16 g_ath[(size_t)NM * NDIM];
__device__ __nv_bfloat16 g_atl[(size_t)NM * NDIM];

// ---------------------------------------------------------------------------
// Helpers (arch-neutral PTX only)
// ---------------------------------------------------------------------------
__device__ __forceinline__ uint32_t smem_u32(const void* p) {
    uint32_t a;
    asm("{ .reg .u64 t; cvta.to.shared.u64 t, %1; cvt.u32.u64 %0, t; }"
        : "=r"(a) : "l"(p));
    return a;
}
__device__ __forceinline__ void cp_async16(uint32_t dst, const void* src) {
    asm volatile("cp.async.cg.shared.global [%0], [%1], 16;"
                 :: "r"(dst), "l"(src));
}
#define CP_COMMIT() asm volatile("cp.async.commit_group;" ::: "memory")
#define CP_WAIT1()  asm volatile("cp.async.wait_group 1;" ::: "memory")
#define CP_WAIT0()  asm volatile("cp.async.wait_group 0;" ::: "memory")

#define LDSM4(r0, r1, r2, r3, addr) \
    asm volatile("ldmatrix.sync.aligned.m8n8.x4.shared.b16 {%0,%1,%2,%3}, [%4];" \
                 : "=r"(r0), "=r"(r1), "=r"(r2), "=r"(r3) : "r"(addr))
#define LDSM4T(r0, r1, r2, r3, addr) \
    asm volatile("ldmatrix.sync.aligned.m8n8.x4.trans.shared.b16 {%0,%1,%2,%3}, [%4];" \
                 : "=r"(r0), "=r"(r1), "=r"(r2), "=r"(r3) : "r"(addr))

__device__ __forceinline__ void mma16816(float* c, const uint32_t* a,
                                         uint32_t b0, uint32_t b1) {
    asm volatile(
        "mma.sync.aligned.m16n8k16.row.col.f32.bf16.bf16.f32 "
        "{%0,%1,%2,%3}, {%4,%5,%6,%7}, {%8,%9}, {%0,%1,%2,%3};"
        : "+f"(c[0]), "+f"(c[1]), "+f"(c[2]), "+f"(c[3])
        : "r"(a[0]), "r"(a[1]), "r"(a[2]), "r"(a[3]), "r"(b0), "r"(b1));
}

// FFMA-only exp2 (no MUFU). Clamps underflow.
__device__ __forceinline__ float fexp2(float x) {
    x = fmaxf(x, -126.0f);
    float r = rintf(x);
    float f = x - r;
    float p =               1.3333558e-3f;
    p = fmaf(p, f, 9.6181291e-3f);
    p = fmaf(p, f, 5.5504109e-2f);
    p = fmaf(p, f, 2.4022651e-1f);
    p = fmaf(p, f, 6.9314718e-1f);
    p = fmaf(p, f, 1.0f);
    return p * __int_as_float(((int)r + 127) << 23);
}

__device__ __forceinline__ void split_pack(uint32_t& hi, uint32_t& lo,
                                           float f0, float f1) {
    __nv_bfloat162 h = __floats2bfloat162_rn(f0, f1);
    __nv_bfloat162 l = __floats2bfloat162_rn(f0 - __bfloat162float(h.x),
                                             f1 - __bfloat162float(h.y));
    hi = *(uint32_t*)&h;
    lo = *(uint32_t*)&l;
}

// ---------------------------------------------------------------------------
// fp32 -> (bf16 hi, bf16 lo) split conversion, vectorized by 4.
// ---------------------------------------------------------------------------
__global__ __launch_bounds__(256) void cvt_split(
    const float4* __restrict__ in, __nv_bfloat162* __restrict__ hi,
    __nv_bfloat162* __restrict__ lo, int n4)
{
    int i = blockIdx.x * blockDim.x + threadIdx.x;
    if (i >= n4) return;
    float4 v = in[i];
    uint32_t h0, l0, h1, l1;
    split_pack(h0, l0, v.x, v.y);
    split_pack(h1, l1, v.z, v.w);
    ((uint32_t*)hi)[2 * i] = h0;  ((uint32_t*)hi)[2 * i + 1] = h1;
    ((uint32_t*)lo)[2 * i] = l0;  ((uint32_t*)lo)[2 * i + 1] = l1;
}

// ---------------------------------------------------------------------------
// bf16x3 MMA GEMM: C[M,N] = A[M,K] x W[N,K]^T + bias
// PERSISTENT: grid = min(ntiles, 2*SMs); each CTA loops over 128x128 tiles,
// eliminating tail-wave quantization (R9: 5.19 waves -> 13.5% idle).
// Inner pipeline identical to R9 (3-stage cp.async, 1 barrier/chunk,
// __launch_bounds__(256,2) pins regs<=128 for 2 CTAs/SM).
// ---------------------------------------------------------------------------
#define KCHUNK   32
#define TILE_B   8192
#define STAGE_B  (4 * TILE_B)
#define NSTAGES  3
#define GEMM_SMEM (NSTAGES * STAGE_B)   // 98304

template <int MODE>
__global__ __launch_bounds__(256, 2) void gemm_mma(
    const __nv_bfloat16* __restrict__ Ah, const __nv_bfloat16* __restrict__ Al,
    const __nv_bfloat16* __restrict__ Bh, const __nv_bfloat16* __restrict__ Bl,
    const float* __restrict__ bias, float* __restrict__ C,
    int M, int N, int K,
    __nv_bfloat16* __restrict__ oqh, __nv_bfloat16* __restrict__ oql,
    __nv_bfloat16* __restrict__ okh, __nv_bfloat16* __restrict__ okl,
    __nv_bfloat16* __restrict__ ovh, __nv_bfloat16* __restrict__ ovl)
{
    extern __shared__ char smem[];
    const uint32_t sbase = smem_u32(smem);
    const int tid  = threadIdx.x;
    const int lane = tid & 31;
    const int wid  = tid >> 5;
    const int wm   = wid & 3;
    const int wn   = wid >> 2;

    const int ntx    = N >> 7;
    const int ntiles = (M >> 7) * ntx;
    const int nchunks = K / KCHUNK;

    const int mi = lane >> 3;
    const int a_row_off = (lane & 7) + ((mi & 1) << 3);
    const int a_ck_off  = mi >> 1;
    const int b_row_off = (lane & 7) + ((mi >> 1) << 3);
    const int b_ck_off  = mi & 1;

    for (int t = blockIdx.x; t < ntiles; t += gridDim.x) {
        const int n0 = (t % ntx) << 7;
        const int m0 = (t / ntx) << 7;

        const __nv_bfloat16* srcs[4] = {
            Ah + (size_t)m0 * K, Al + (size_t)m0 * K,
            Bh + (size_t)n0 * K, Bl + (size_t)n0 * K };

        auto issue = [&](int chunk, int stage) {
            const int k0 = chunk * KCHUNK;
            const uint32_t sb = sbase + stage * STAGE_B;
            #pragma unroll
            for (int i = 0; i < 8; i++) {
                const int part = i >> 1;
                int j   = ((i & 1) << 8) + tid;
                int row = j >> 2;
                int c   = j & 3;
                const char* src = (const char*)(srcs[part] + (size_t)row * K + k0)
                                  + c * 16;
                uint32_t dst = sb + part * TILE_B + row * 64
                               + ((c ^ ((row >> 1) & 3)) << 4);
                cp_async16(dst, src);
            }
            CP_COMMIT();
        };

        // Protect smem stages from previous tile's slowest warp.
        __syncthreads();

        issue(0, 0);
        issue(1, 1);

        float acc[2][8][4];
        #pragma unroll
        for (int mf = 0; mf < 2; mf++)
            #pragma unroll
            for (int nf = 0; nf < 8; nf++)
                #pragma unroll
                for (int r = 0; r < 4; r++) acc[mf][nf][r] = 0.f;

        for (int ch = 0; ch < nchunks; ch++) {
            if (ch + 1 < nchunks) { CP_WAIT1(); } else { CP_WAIT0(); }
            __syncthreads();
            if (ch + 2 < nchunks) issue(ch + 2, (ch + 2) % NSTAGES);

            const uint32_t sb  = sbase + (ch % NSTAGES) * STAGE_B;
            const uint32_t aH = sb, aL = sb + TILE_B;
            const uint32_t bH = sb + 2 * TILE_B, bL = sb + 3 * TILE_B;

            #pragma unroll
            for (int ks = 0; ks < 2; ks++) {
                uint32_t ah[2][4], al[2][4], bh[8][2], bl[8][2];
                #pragma unroll
                for (int mf = 0; mf < 2; mf++) {
                    int r  = wm * 32 + mf * 16 + a_row_off;
                    int ck = ks * 2 + a_ck_off;
                    uint32_t off = r * 64 + ((ck ^ ((r >> 1) & 3)) << 4);
                    LDSM4(ah[mf][0], ah[mf][1], ah[mf][2], ah[mf][3], aH + off);
                    LDSM4(al[mf][0], al[mf][1], al[mf][2], al[mf][3], aL + off);
                }
                #pragma unroll
                for (int np = 0; np < 4; np++) {
                    int r  = wn * 64 + np * 16 + b_row_off;
                    int ck = ks * 2 + b_ck_off;
                    uint32_t off = r * 64 + ((ck ^ ((r >> 1) & 3)) << 4);
                    LDSM4(bh[np * 2][0], bh[np * 2][1],
                          bh[np * 2 + 1][0], bh[np * 2 + 1][1], bH + off);
                    LDSM4(bl[np * 2][0], bl[np * 2][1],
                          bl[np * 2 + 1][0], bl[np * 2 + 1][1], bL + off);
                }
                #pragma unroll
                for (int mf = 0; mf < 2; mf++)
                    #pragma unroll
                    for (int nf = 0; nf < 8; nf++) {
                        mma16816(acc[mf][nf], ah[mf], bh[nf][0], bh[nf][1]);
                        mma16816(acc[mf][nf], ah[mf], bl[nf][0], bl[nf][1]);
                        mma16816(acc[mf][nf], al[mf], bh[nf][0], bh[nf][1]);
                    }
            }
        }

        const int crow = m0 + wm * 32 + (lane >> 2);
        const int ccol = n0 + wn * 64 + (lane & 3) * 2;

        if (MODE == 0) {
            #pragma unroll
            for (int nf = 0; nf < 8; nf++) {
                float2 bv = *(const float2*)&bias[ccol + nf * 8];
                #pragma unroll
                for (int mf = 0; mf < 2; mf++) {
                    float* c0 = C + (size_t)(crow + mf * 16) * N + ccol + nf * 8;
                    float* c1 = C + (size_t)(crow + mf * 16 + 8) * N + ccol + nf * 8;
                    *(float2*)c0 = make_float2(acc[mf][nf][0] + bv.x,
                                               acc[mf][nf][1] + bv.y);
                    *(float2*)c1 = make_float2(acc[mf][nf][2] + bv.x,
                                               acc[mf][nf][3] + bv.y);
                }
            }
        } else {
            const int sel = ccol >> 10;
            const int hh  = (ccol >> 6) & 15;
            const int d0  = ccol & 63;
            __nv_bfloat16* dh = (sel == 0) ? oqh : (sel == 1) ? okh : ovh;
            __nv_bfloat16* dl = (sel == 0) ? oql : (sel == 1) ? okl : ovl;
            #pragma unroll
            for (int nf = 0; nf < 8; nf++) {
                float2 bv = *(const float2*)&bias[ccol + nf * 8];
                #pragma unroll
                for (int mf = 0; mf < 2; mf++) {
                    #pragma unroll
                    for (int rr = 0; rr < 2; rr++) {
                        int row = crow + mf * 16 + rr * 8;
                        int b   = row >> 11, l = row & 2047;
                        size_t base = (((size_t)(b * 16 + hh)) * 2048 + l) * 64
                                      + d0 + nf * 8;
                        uint32_t h, lo;
                        split_pack(h, lo, acc[mf][nf][rr * 2] + bv.x,
                                          acc[mf][nf][rr * 2 + 1] + bv.y);
                        *(uint32_t*)(dh + base) = h;
                        *(uint32_t*)(dl + base) = lo;
                    }
                }
            }
        }
    }
}

// ---------------------------------------------------------------------------
// MMA causal flash attention (bf16x3, FFMA exp2), STATIC-MAX softmax.
// (unchanged from R9)
// ---------------------------------------------------------------------------
#define A_QH      0
#define A_QL      16384
#define ATT_KV0   32768
#define ATT_STAGE 32768
#define ATT_SMEM  (ATT_KV0 + 2 * ATT_STAGE)   // 98304

__device__ __forceinline__ uint32_t swoff(int row, int c) {
    return row * 128 + ((c ^ (row & 7)) << 4);
}

__global__ __launch_bounds__(256) void attn_mma(
    const __nv_bfloat16* __restrict__ qh_g, const __nv_bfloat16* __restrict__ ql_g,
    const __nv_bfloat16* __restrict__ kh_g, const __nv_bfloat16* __restrict__ kl_g,
    const __nv_bfloat16* __restrict__ vh_g, const __nv_bfloat16* __restrict__ vl_g,
    __nv_bfloat16* __restrict__ ath, __nv_bfloat16* __restrict__ atl)
{
    extern __shared__ __align__(16) char sm_a[];
    const uint32_t S = smem_u32(sm_a);
    const int tid  = threadIdx.x;
    const int lane = tid & 31;
    const int w    = tid >> 5;
    const int qi   = (int)gridDim.x - 1 - (int)blockIdx.x;  // long first
    const int q0   = qi * 128;
    const int by   = blockIdx.y;          // b*16 + h
    const size_t o = (size_t)by * NL * HDIM;

    auto issue_kv = [&](int kt, int stage) {
        const int kb = kt * 64;
        const uint32_t KB = S + ATT_KV0 + stage * ATT_STAGE;
        const char* p0 = (const char*)(kh_g + o + (size_t)kb * 64);
        const char* p1 = (const char*)(kl_g + o + (size_t)kb * 64);
        const char* p2 = (const char*)(vh_g + o + (size_t)kb * 64);
        const char* p3 = (const char*)(vl_g + o + (size_t)kb * 64);
        #pragma unroll
        for (int j = 0; j < 2; j++) {
            int i = tid + j * 256, row = i >> 3, c = i & 7;
            uint32_t d = swoff(row, c);
            int go = row * 128 + c * 16;
            cp_async16(KB + d,         p0 + go);
            cp_async16(KB + 8192 + d,  p1 + go);
            cp_async16(KB + 16384 + d, p2 + go);
            cp_async16(KB + 24576 + d, p3 + go);
        }
        CP_COMMIT();
    };

    // Prologue: Q tile (128 rows, hi/lo) + KV tile 0 in one cp.async group.
    {
        const char* qhp = (const char*)(qh_g + o + (size_t)q0 * 64);
        const char* qlp = (const char*)(ql_g + o + (size_t)q0 * 64);
        #pragma unroll
        for (int j = 0; j < 4; j++) {
            int i = tid + j * 256, row = i >> 3, c = i & 7;
            uint32_t d = swoff(row, c);
            cp_async16(S + A_QH + d, qhp + row * 128 + c * 16);
            cp_async16(S + A_QL + d, qlp + row * 128 + c * 16);
        }
        issue_kv(0, 0);   // commits the combined group
        CP_WAIT0();
        __syncthreads();
    }

    // Hoist Q fragments (invariant over kt loop). Warp w owns rows w*16..+15.
    uint32_t qfh[4][4], qfl[4][4];
    #pragma unroll
    for (int ks = 0; ks < 4; ks++) {
        int row = w * 16 + (lane & 15);
        int ch  = ks * 2 + (lane >> 4);
        uint32_t off = swoff(row, ch);
        LDSM4(qfh[ks][0], qfh[ks][1], qfh[ks][2], qfh[ks][3], S + A_QH + off);
        LDSM4(qfl[ks][0], qfl[ks][1], qfl[ks][2], qfl[ks][3], S + A_QL + off);
    }

    float acc[8][4];
    #pragma unroll
    for (int nf = 0; nf < 8; nf++)
        #pragma unroll
        for (int r = 0; r < 4; r++) acc[nf][r] = 0.f;
    float l_run0 = 0.f, l_run1 = 0.f;

    const float k2s  = 0.125f * 1.4426950408889634f;  // SCALE * log2(e)
    const int   wrow = q0 + w * 16;                   // warp's min row
    const int   row0 = wrow + (lane >> 2);
    const int   row1 = row0 + 8;
    const int   nt   = 2 * qi + 2;

    for (int kt = 0; kt < nt; kt++) {
        if (kt > 0) {
            CP_WAIT0();        // tile kt landed (prefetched during kt-1)
            __syncthreads();   // all warps done reading stage (kt+1)&1
        }
        if (kt + 1 < nt) issue_kv(kt + 1, (kt + 1) & 1);

        const int kb = kt * 64;
        if (kb <= wrow + 15) {             // warp has at least one visible key
            const uint32_t KB = S + ATT_KV0 + (kt & 1) * ATT_STAGE;
            const uint32_t KH = KB, KL = KB + 8192;
            const uint32_t VH = KB + 16384, VL = KB + 24576;

            // ---- S = Q . K^T (bf16x3) ----
            float s[8][4];
            #pragma unroll
            for (int nf = 0; nf < 8; nf++)
                #pragma unroll
                for (int r = 0; r < 4; r++) s[nf][r] = 0.f;

            #pragma unroll
            for (int ks = 0; ks < 4; ks++) {
                #pragma unroll
                for (int kg = 0; kg < 4; kg++) {
                    int row = kg * 16 + (lane & 7) + ((lane >> 4) << 3);
                    int ch  = ks * 2 + ((lane >> 3) & 1);
                    uint32_t off = swoff(row, ch);
                    uint32_t kbh[4], kbl[4];
                    LDSM4(kbh[0], kbh[1], kbh[2], kbh[3], KH + off);
                    LDSM4(kbl[0], kbl[1], kbl[2], kbl[3], KL + off);
                    mma16816(s[2 * kg],     qfh[ks], kbh[0], kbh[1]);
                    mma16816(s[2 * kg],     qfh[ks], kbl[0], kbl[1]);
                    mma16816(s[2 * kg],     qfl[ks], kbh[0], kbh[1]);
                    mma16816(s[2 * kg + 1], qfh[ks], kbh[2], kbh[3]);
                    mma16816(s[2 * kg + 1], qfh[ks], kbl[2], kbl[3]);
                    mma16816(s[2 * kg + 1], qfl[ks], kbh[2], kbh[3]);
                }
            }

            // ---- scale + causal mask (static max: no running rescale) ----
            if (kb + 63 > wrow) {          // tile straddles diagonal for warp
                #pragma unroll
                for (int nf = 0; nf < 8; nf++) {
                    int key = kb + nf * 8 + (lane & 3) * 2;
                    s[nf][0] = (key     <= row0) ? s[nf][0] * k2s : -1e30f;
                    s[nf][1] = (key + 1 <= row0) ? s[nf][1] * k2s : -1e30f;
                    s[nf][2] = (key     <= row1) ? s[nf][2] * k2s : -1e30f;
                    s[nf][3] = (key + 1 <= row1) ? s[nf][3] * k2s : -1e30f;
                }
            } else {
                #pragma unroll
                for (int nf = 0; nf < 8; nf++)
                    #pragma unroll
                    for (int r = 0; r < 4; r++) s[nf][r] *= k2s;
            }

            // ---- p = exp2(logit), row sums ----
            float ls0 = 0.f, ls1 = 0.f;
            #pragma unroll
            for (int nf = 0; nf < 8; nf++) {
                s[nf][0] = fexp2(s[nf][0]);
                s[nf][1] = fexp2(s[nf][1]);
                s[nf][2] = fexp2(s[nf][2]);
                s[nf][3] = fexp2(s[nf][3]);
                ls0 += s[nf][0] + s[nf][1];
                ls1 += s[nf][2] + s[nf][3];
            }
            ls0 += __shfl_xor_sync(0xffffffffu, ls0, 1);
            ls0 += __shfl_xor_sync(0xffffffffu, ls0, 2);
            ls1 += __shfl_xor_sync(0xffffffffu, ls1, 1);
            ls1 += __shfl_xor_sync(0xffffffffu, ls1, 2);
            l_run0 += ls0;
            l_run1 += ls1;

            // ---- acc += P . V (bf16x3) ----
            #pragma unroll
            for (int kc = 0; kc < 4; kc++) {
                uint32_t pah[4], pal[4];
                split_pack(pah[0], pal[0], s[2 * kc][0],     s[2 * kc][1]);
                split_pack(pah[1], pal[1], s[2 * kc][2],     s[2 * kc][3]);
                split_pack(pah[2], pal[2], s[2 * kc + 1][0], s[2 * kc + 1][1]);
                split_pack(pah[3], pal[3], s[2 * kc + 1][2], s[2 * kc + 1][3]);
                #pragma unroll
                for (int np = 0; np < 4; np++) {
                    int row = kc * 16 + (lane & 15);
                    int ch  = np * 2 + (lane >> 4);
                    uint32_t off = swoff(row, ch);
                    uint32_t vbh[4], vbl[4];
                    LDSM4T(vbh[0], vbh[1], vbh[2], vbh[3], VH + off);
                    LDSM4T(vbl[0], vbl[1], vbl[2], vbl[3], VL + off);
                    mma16816(acc[2 * np],     pah, vbh[0], vbh[1]);
                    mma16816(acc[2 * np],     pah, vbl[0], vbl[1]);
                    mma16816(acc[2 * np],     pal, vbh[0], vbh[1]);
                    mma16816(acc[2 * np + 1], pah, vbh[2], vbh[3]);
                    mma16816(acc[2 * np + 1], pah, vbl[2], vbl[3]);
                    mma16816(acc[2 * np + 1], pal, vbh[2], vbh[3]);
                }
            }
        }
    }

    // ---- epilogue: normalize, split hi/lo, store to ath/atl [8192,1024] ----
    const float i0 = 1.0f / l_run0;
    const float i1 = 1.0f / l_run1;
    const int b  = by >> 4;
    const int hh = by & 15;
    const int mr0 = b * NL + row0;
    const int mr1 = b * NL + row1;
    const int col = hh * 64 + (lane & 3) * 2;
    #pragma unroll
    for (int nf = 0; nf < 8; nf++) {
        uint32_t h, lo;
        split_pack(h, lo, acc[nf][0] * i0, acc[nf][1] * i0);
        *(uint32_t*)(ath + (size_t)mr0 * NDIM + col + nf * 8) = h;
        *(uint32_t*)(atl + (size_t)mr0 * NDIM + col + nf * 8) = lo;
        split_pack(h, lo, acc[nf][2] * i1, acc[nf][3] * i1);
        *(uint32_t*)(ath + (size_t)mr1 * NDIM + col + nf * 8) = h;
        *(uint32_t*)(atl + (size_t)mr1 * NDIM + col + nf * 8) = lo;
    }
}

// ---------------------------------------------------------------------------
// kernel_launch
// Inputs: [0]=x f32, [1]=attn_mask i32 (implicit tril, unused),
//         [2]=qkv_w, [3]=qkv_b, [4]=proj_w, [5]=proj_b. Output f32 [8192,1024].
// ---------------------------------------------------------------------------
extern "C" void kernel_launch(void* const* d_in, const int* in_sizes, int n_in,
                              void* d_out, int out_size)
{
    (void)in_sizes; (void)n_in; (void)out_size;
    const float* x      = (const float*)d_in[0];
    const float* qkv_w  = (const float*)d_in[2];
    const float* qkv_b  = (const float*)d_in[3];
    const float* proj_w = (const float*)d_in[4];
    const float* proj_b = (const float*)d_in[5];
    float* out = (float*)d_out;

    __nv_bfloat16 *xh, *xl, *wqh, *wql, *wph, *wpl;
    __nv_bfloat16 *qh, *ql, *kh, *kl, *vh, *vl, *ath, *atl;
    cudaGetSymbolAddress((void**)&xh, g_xh);
    cudaGetSymbolAddress((void**)&xl, g_xl);
    cudaGetSymbolAddress((void**)&wqh, g_wqh);
    cudaGetSymbolAddress((void**)&wql, g_wql);
    cudaGetSymbolAddress((void**)&wph, g_wph);
    cudaGetSymbolAddress((void**)&wpl, g_wpl);
    cudaGetSymbolAddress((void**)&qh, g_qh);
    cudaGetSymbolAddress((void**)&ql, g_ql);
    cudaGetSymbolAddress((void**)&kh, g_kh);
    cudaGetSymbolAddress((void**)&kl, g_kl);
    cudaGetSymbolAddress((void**)&vh, g_vh);
    cudaGetSymbolAddress((void**)&vl, g_vl);
    cudaGetSymbolAddress((void**)&ath, g_ath);
    cudaGetSymbolAddress((void**)&atl, g_atl);

    cudaFuncSetAttribute(gemm_mma<0>,
                         cudaFuncAttributeMaxDynamicSharedMemorySize, GEMM_SMEM);
    cudaFuncSetAttribute(gemm_mma<1>,
                         cudaFuncAttributeMaxDynamicSharedMemorySize, GEMM_SMEM);
    cudaFuncSetAttribute(attn_mma,
                         cudaFuncAttributeMaxDynamicSharedMemorySize, ATT_SMEM);

    int nsm = 148;
    cudaDeviceGetAttribute(&nsm, cudaDevAttrMultiProcessorCount, 0);
    const int pgrid = 2 * nsm;   // 2 CTAs/SM persistent

    // Split inputs to bf16 hi/lo
    int n4x = NM * NDIM / 4;
    cvt_split<<<n4x / 256, 256>>>((const float4*)x, (__nv_bfloat162*)xh,
                                  (__nv_bfloat162*)xl, n4x);
    int n4wq = QKV_N * NDIM / 4;
    cvt_split<<<n4wq / 256, 256>>>((const float4*)qkv_w, (__nv_bfloat162*)wqh,
                                   (__nv_bfloat162*)wql, n4wq);
    int n4wp = NDIM * NDIM / 4;
    cvt_split<<<n4wp / 256, 256>>>((const float4*)proj_w, (__nv_bfloat162*)wph,
                                   (__nv_bfloat162*)wpl, n4wp);

    // QKV projection -> split q/k/v buffers in [B,H,L,64] layout (persistent)
    int t_qkv = (QKV_N / 128) * (NM / 128);   // 1536 tiles
    gemm_mma<1><<<(t_qkv < pgrid ? t_qkv : pgrid), 256, GEMM_SMEM>>>(
        xh, xl, wqh, wql, qkv_b, nullptr, NM, QKV_N, NDIM,
        qh, ql, kh, kl, vh, vl);

    // Causal MMA attention (128-row q tiles) -> ath/atl
    attn_mma<<<dim3(NL / 128, NB * NHEADS), 256, ATT_SMEM>>>(
        qh, ql, kh, kl, vh, vl, ath, atl);

    // Output projection -> fp32 out (persistent)
    int t_proj = (NDIM / 128) * (NM / 128);   // 512 tiles
    gemm_mma<0><<<(t_proj < pgrid ? t_proj : pgrid), 256, GEMM_SMEM>>>(
        ath, atl, wph, wpl, proj_b, out, NM, NDIM, NDIM,
        nullptr, nullptr, nullptr, nullptr, nullptr, nullptr);
}

// round 12
// speedup vs baseline: 1.0042x; 1.0042x over previous
#include <cuda_runtime.h>
#include <cuda_bf16.h>
#include <cstdint>

#define NDIM   1024
#define NHEADS 16
#define HDIM   64
#define NB     4
#define NL     2048
#define NM     (NB * NL)        // 8192 rows
#define QKV_N  (3 * NDIM)       // 3072

// ---------------------------------------------------------------------------
// Scratch (allocation-free rule: static __device__ globals)
// ---------------------------------------------------------------------------
__device__ __nv_bfloat16 g_xh[(size_t)NM * NDIM];
__device__ __nv_bfloat16 g_xl[(size_t)NM * NDIM];
__device__ __nv_bfloat16 g_wqh[(size_t)QKV_N * NDIM];
__device__ __nv_bfloat16 g_wql[(size_t)QKV_N * NDIM];
__device__ __nv_bfloat16 g_wph[(size_t)NDIM * NDIM];
__device__ __nv_bfloat16 g_wpl[(size_t)NDIM * NDIM];
// q/k/v hi/lo in [B,H,L,64] layout (written by qkv GEMM epilogue)
__device__ __nv_bfloat16 g_qh[(size_t)NB * NHEADS * NL * HDIM];
__device__ __nv_bfloat16 g_ql[(size_t)NB * NHEADS * NL * HDIM];
__device__ __nv_bfloat16 g_kh[(size_t)NB * NHEADS * NL * HDIM];
__device__ __nv_bfloat16 g_kl[(size_t)NB * NHEADS * NL * HDIM];
__device__ __nv_bfloat16 g_vh[(size_t)NB * NHEADS * NL * HDIM];
__device__ __nv_bfloat16 g_vl[(size_t)NB * NHEADS * NL * HDIM];
// attention output hi/lo [8192,1024] (input to proj GEMM)
__device__ __nv_bfloat16 g_ath[(size_t)NM * NDIM];
__device__ __nv_bfloat16 g_atl[(size_t)NM * NDIM];

// ---------------------------------------------------------------------------
// Helpers (arch-neutral PTX only)
// ---------------------------------------------------------------------------
__device__ __forceinline__ uint32_t smem_u32(const void* p) {
    uint32_t a;
    asm("{ .reg .u64 t; cvta.to.shared.u64 t, %1; cvt.u32.u64 %0, t; }"
        : "=r"(a) : "l"(p));
    return a;
}
__device__ __forceinline__ void cp_async16(uint32_t dst, const void* src) {
    asm volatile("cp.async.cg.shared.global [%0], [%1], 16;"
                 :: "r"(dst), "l"(src));
}
#define CP_COMMIT() asm volatile("cp.async.commit_group;" ::: "memory")
#define CP_WAIT1()  asm volatile("cp.async.wait_group 1;" ::: "memory")
#define CP_WAIT0()  asm volatile("cp.async.wait_group 0;" ::: "memory")

#define LDSM4(r0, r1, r2, r3, addr) \
    asm volatile("ldmatrix.sync.aligned.m8n8.x4.shared.b16 {%0,%1,%2,%3}, [%4];" \
                 : "=r"(r0), "=r"(r1), "=r"(r2), "=r"(r3) : "r"(addr))
#define LDSM4T(r0, r1, r2, r3, addr) \
    asm volatile("ldmatrix.sync.aligned.m8n8.x4.trans.shared.b16 {%0,%1,%2,%3}, [%4];" \
                 : "=r"(r0), "=r"(r1), "=r"(r2), "=r"(r3) : "r"(addr))

__device__ __forceinline__ void mma16816(float* c, const uint32_t* a,
                                         uint32_t b0, uint32_t b1) {
    asm volatile(
        "mma.sync.aligned.m16n8k16.row.col.f32.bf16.bf16.f32 "
        "{%0,%1,%2,%3}, {%4,%5,%6,%7}, {%8,%9}, {%0,%1,%2,%3};"
        : "+f"(c[0]), "+f"(c[1]), "+f"(c[2]), "+f"(c[3])
        : "r"(a[0]), "r"(a[1]), "r"(a[2]), "r"(a[3]), "r"(b0), "r"(b1));
}

// FFMA-only exp2 (no MUFU). Clamps underflow.
__device__ __forceinline__ float fexp2(float x) {
    x = fmaxf(x, -126.0f);
    float r = rintf(x);
    float f = x - r;
    float p =               1.3333558e-3f;
    p = fmaf(p, f, 9.6181291e-3f);
    p = fmaf(p, f, 5.5504109e-2f);
    p = fmaf(p, f, 2.4022651e-1f);
    p = fmaf(p, f, 6.9314718e-1f);
    p = fmaf(p, f, 1.0f);
    return p * __int_as_float(((int)r + 127) << 23);
}

__device__ __forceinline__ void split_pack(uint32_t& hi, uint32_t& lo,
                                           float f0, float f1) {
    __nv_bfloat162 h = __floats2bfloat162_rn(f0, f1);
    __nv_bfloat162 l = __floats2bfloat162_rn(f0 - __bfloat162float(h.x),
                                             f1 - __bfloat162float(h.y));
    hi = *(uint32_t*)&h;
    lo = *(uint32_t*)&l;
}

// ---------------------------------------------------------------------------
// fp32 -> (bf16 hi, bf16 lo) split conversion, vectorized by 4.
// ---------------------------------------------------------------------------
__global__ __launch_bounds__(256) void cvt_split(
    const float4* __restrict__ in, __nv_bfloat162* __restrict__ hi,
    __nv_bfloat162* __restrict__ lo, int n4)
{
    int i = blockIdx.x * blockDim.x + threadIdx.x;
    if (i >= n4) return;
    float4 v = in[i];
    uint32_t h0, l0, h1, l1;
    split_pack(h0, l0, v.x, v.y);
    split_pack(h1, l1, v.z, v.w);
    ((uint32_t*)hi)[2 * i] = h0;  ((uint32_t*)hi)[2 * i + 1] = h1;
    ((uint32_t*)lo)[2 * i] = l0;  ((uint32_t*)lo)[2 * i + 1] = l1;
}

// ---------------------------------------------------------------------------
// bf16x3 MMA GEMM: C[M,N] = A[M,K] x W[N,K]^T + bias
// R9 launch config (one CTA per 128x128 tile). MMA issue reordered into
// THREE PASSES (AhBh x16, AhBl x16, AlBh x16) so consecutive MMAs hit
// different accumulators (same-acc reuse distance 1 -> 16).
// ---------------------------------------------------------------------------
#define KCHUNK   32
#define TILE_B   8192
#define STAGE_B  (4 * TILE_B)
#define NSTAGES  3
#define GEMM_SMEM (NSTAGES * STAGE_B)   // 98304

template <int MODE>
__global__ __launch_bounds__(256, 2) void gemm_mma(
    const __nv_bfloat16* __restrict__ Ah, const __nv_bfloat16* __restrict__ Al,
    const __nv_bfloat16* __restrict__ Bh, const __nv_bfloat16* __restrict__ Bl,
    const float* __restrict__ bias, float* __restrict__ C, int N, int K,
    __nv_bfloat16* __restrict__ oqh, __nv_bfloat16* __restrict__ oql,
    __nv_bfloat16* __restrict__ okh, __nv_bfloat16* __restrict__ okl,
    __nv_bfloat16* __restrict__ ovh, __nv_bfloat16* __restrict__ ovl)
{
    extern __shared__ char smem[];
    const uint32_t sbase = smem_u32(smem);
    const int tid  = threadIdx.x;
    const int lane = tid & 31;
    const int wid  = tid >> 5;
    const int wm   = wid & 3;
    const int wn   = wid >> 2;
    const int m0   = blockIdx.y * 128;
    const int n0   = blockIdx.x * 128;

    const __nv_bfloat16* srcs[4] = {
        Ah + (size_t)m0 * K, Al + (size_t)m0 * K,
        Bh + (size_t)n0 * K, Bl + (size_t)n0 * K };

    const int nchunks = K / KCHUNK;

    auto issue = [&](int chunk, int stage) {
        const int k0 = chunk * KCHUNK;
        const uint32_t sb = sbase + stage * STAGE_B;
        #pragma unroll
        for (int i = 0; i < 8; i++) {
            const int part = i >> 1;
            int j   = ((i & 1) << 8) + tid;
            int row = j >> 2;
            int c   = j & 3;
            const char* src = (const char*)(srcs[part] + (size_t)row * K + k0)
                              + c * 16;
            uint32_t dst = sb + part * TILE_B + row * 64
                           + ((c ^ ((row >> 1) & 3)) << 4);
            cp_async16(dst, src);
        }
        CP_COMMIT();
    };

    float acc[2][8][4];
    #pragma unroll
    for (int mf = 0; mf < 2; mf++)
        #pragma unroll
        for (int nf = 0; nf < 8; nf++)
            #pragma unroll
            for (int r = 0; r < 4; r++) acc[mf][nf][r] = 0.f;

    const int mi = lane >> 3;
    const int a_row_off = (lane & 7) + ((mi & 1) << 3);
    const int a_ck_off  = mi >> 1;
    const int b_row_off = (lane & 7) + ((mi >> 1) << 3);
    const int b_ck_off  = mi & 1;

    issue(0, 0);
    issue(1, 1);

    for (int ch = 0; ch < nchunks; ch++) {
        if (ch + 1 < nchunks) { CP_WAIT1(); } else { CP_WAIT0(); }
        __syncthreads();
        if (ch + 2 < nchunks) issue(ch + 2, (ch + 2) % NSTAGES);

        const uint32_t sb  = sbase + (ch % NSTAGES) * STAGE_B;
        const uint32_t aH = sb, aL = sb + TILE_B;
        const uint32_t bH = sb + 2 * TILE_B, bL = sb + 3 * TILE_B;

        #pragma unroll
        for (int ks = 0; ks < 2; ks++) {
            uint32_t ah[2][4], al[2][4], bh[8][2], bl[8][2];
            #pragma unroll
            for (int mf = 0; mf < 2; mf++) {
                int r  = wm * 32 + mf * 16 + a_row_off;
                int ck = ks * 2 + a_ck_off;
                uint32_t off = r * 64 + ((ck ^ ((r >> 1) & 3)) << 4);
                LDSM4(ah[mf][0], ah[mf][1], ah[mf][2], ah[mf][3], aH + off);
                LDSM4(al[mf][0], al[mf][1], al[mf][2], al[mf][3], aL + off);
            }
            #pragma unroll
            for (int np = 0; np < 4; np++) {
                int r  = wn * 64 + np * 16 + b_row_off;
                int ck = ks * 2 + b_ck_off;
                uint32_t off = r * 64 + ((ck ^ ((r >> 1) & 3)) << 4);
                LDSM4(bh[np * 2][0], bh[np * 2][1],
                      bh[np * 2 + 1][0], bh[np * 2 + 1][1], bH + off);
                LDSM4(bl[np * 2][0], bl[np * 2][1],
                      bl[np * 2 + 1][0], bl[np * 2 + 1][1], bL + off);
            }
            // Pass 1: Ah*Bh (16 independent MMAs)
            #pragma unroll
            for (int mf = 0; mf < 2; mf++)
                #pragma unroll
                for (int nf = 0; nf < 8; nf++)
                    mma16816(acc[mf][nf], ah[mf], bh[nf][0], bh[nf][1]);
            // Pass 2: Ah*Bl
            #pragma unroll
            for (int mf = 0; mf < 2; mf++)
                #pragma unroll
                for (int nf = 0; nf < 8; nf++)
                    mma16816(acc[mf][nf], ah[mf], bl[nf][0], bl[nf][1]);
            // Pass 3: Al*Bh
            #pragma unroll
            for (int mf = 0; mf < 2; mf++)
                #pragma unroll
                for (int nf = 0; nf < 8; nf++)
                    mma16816(acc[mf][nf], al[mf], bh[nf][0], bh[nf][1]);
        }
    }

    const int crow = m0 + wm * 32 + (lane >> 2);
    const int ccol = n0 + wn * 64 + (lane & 3) * 2;

    if (MODE == 0) {
        #pragma unroll
        for (int nf = 0; nf < 8; nf++) {
            float2 bv = *(const float2*)&bias[ccol + nf * 8];
            #pragma unroll
            for (int mf = 0; mf < 2; mf++) {
                float* c0 = C + (size_t)(crow + mf * 16) * N + ccol + nf * 8;
                float* c1 = C + (size_t)(crow + mf * 16 + 8) * N + ccol + nf * 8;
                *(float2*)c0 = make_float2(acc[mf][nf][0] + bv.x,
                                           acc[mf][nf][1] + bv.y);
                *(float2*)c1 = make_float2(acc[mf][nf][2] + bv.x,
                                           acc[mf][nf][3] + bv.y);
            }
        }
    } else {
        const int sel = ccol >> 10;
        const int hh  = (ccol >> 6) & 15;
        const int d0  = ccol & 63;
        __nv_bfloat16* dh = (sel == 0) ? oqh : (sel == 1) ? okh : ovh;
        __nv_bfloat16* dl = (sel == 0) ? oql : (sel == 1) ? okl : ovl;
        #pragma unroll
        for (int nf = 0; nf < 8; nf++) {
            float2 bv = *(const float2*)&bias[ccol + nf * 8];
            #pragma unroll
            for (int mf = 0; mf < 2; mf++) {
                #pragma unroll
                for (int rr = 0; rr < 2; rr++) {
                    int row = crow + mf * 16 + rr * 8;
                    int b   = row >> 11, l = row & 2047;
                    size_t base = (((size_t)(b * 16 + hh)) * 2048 + l) * 64
                                  + d0 + nf * 8;
                    uint32_t h, lo;
                    split_pack(h, lo, acc[mf][nf][rr * 2] + bv.x,
                                      acc[mf][nf][rr * 2 + 1] + bv.y);
                    *(uint32_t*)(dh + base) = h;
                    *(uint32_t*)(dl + base) = lo;
                }
            }
        }
    }
}

// ---------------------------------------------------------------------------
// MMA causal flash attention (bf16x3, FFMA exp2), STATIC-MAX softmax.
// R9 structure; MMA issue interleaved (same-acc distance 1 -> 2).
// ---------------------------------------------------------------------------
#define A_QH      0
#define A_QL      16384
#define ATT_KV0   32768
#define ATT_STAGE 32768
#define ATT_SMEM  (ATT_KV0 + 2 * ATT_STAGE)   // 98304

__device__ __forceinline__ uint32_t swoff(int row, int c) {
    return row * 128 + ((c ^ (row & 7)) << 4);
}

__global__ __launch_bounds__(256) void attn_mma(
    const __nv_bfloat16* __restrict__ qh_g, const __nv_bfloat16* __restrict__ ql_g,
    const __nv_bfloat16* __restrict__ kh_g, const __nv_bfloat16* __restrict__ kl_g,
    const __nv_bfloat16* __restrict__ vh_g, const __nv_bfloat16* __restrict__ vl_g,
    __nv_bfloat16* __restrict__ ath, __nv_bfloat16* __restrict__ atl)
{
    extern __shared__ __align__(16) char sm_a[];
    const uint32_t S = smem_u32(sm_a);
    const int tid  = threadIdx.x;
    const int lane = tid & 31;
    const int w    = tid >> 5;
    const int qi   = (int)gridDim.x - 1 - (int)blockIdx.x;  // long first
    const int q0   = qi * 128;
    const int by   = blockIdx.y;          // b*16 + h
    const size_t o = (size_t)by * NL * HDIM;

    auto issue_kv = [&](int kt, int stage) {
        const int kb = kt * 64;
        const uint32_t KB = S + ATT_KV0 + stage * ATT_STAGE;
        const char* p0 = (const char*)(kh_g + o + (size_t)kb * 64);
        const char* p1 = (const char*)(kl_g + o + (size_t)kb * 64);
        const char* p2 = (const char*)(vh_g + o + (size_t)kb * 64);
        const char* p3 = (const char*)(vl_g + o + (size_t)kb * 64);
        #pragma unroll
        for (int j = 0; j < 2; j++) {
            int i = tid + j * 256, row = i >> 3, c = i & 7;
            uint32_t d = swoff(row, c);
            int go = row * 128 + c * 16;
            cp_async16(KB + d,         p0 + go);
            cp_async16(KB + 8192 + d,  p1 + go);
            cp_async16(KB + 16384 + d, p2 + go);
            cp_async16(KB + 24576 + d, p3 + go);
        }
        CP_COMMIT();
    };

    // Prologue: Q tile (128 rows, hi/lo) + KV tile 0 in one cp.async group.
    {
        const char* qhp = (const char*)(qh_g + o + (size_t)q0 * 64);
        const char* qlp = (const char*)(ql_g + o + (size_t)q0 * 64);
        #pragma unroll
        for (int j = 0; j < 4; j++) {
            int i = tid + j * 256, row = i >> 3, c = i & 7;
            uint32_t d = swoff(row, c);
            cp_async16(S + A_QH + d, qhp + row * 128 + c * 16);
            cp_async16(S + A_QL + d, qlp + row * 128 + c * 16);
        }
        issue_kv(0, 0);   // commits the combined group
        CP_WAIT0();
        __syncthreads();
    }

    // Hoist Q fragments (invariant over kt loop). Warp w owns rows w*16..+15.
    uint32_t qfh[4][4], qfl[4][4];
    #pragma unroll
    for (int ks = 0; ks < 4; ks++) {
        int row = w * 16 + (lane & 15);
        int ch  = ks * 2 + (lane >> 4);
        uint32_t off = swoff(row, ch);
        LDSM4(qfh[ks][0], qfh[ks][1], qfh[ks][2], qfh[ks][3], S + A_QH + off);
        LDSM4(qfl[ks][0], qfl[ks][1], qfl[ks][2], qfl[ks][3], S + A_QL + off);
    }

    float acc[8][4];
    #pragma unroll
    for (int nf = 0; nf < 8; nf++)
        #pragma unroll
        for (int r = 0; r < 4; r++) acc[nf][r] = 0.f;
    float l_run0 = 0.f, l_run1 = 0.f;

    const float k2s  = 0.125f * 1.4426950408889634f;  // SCALE * log2(e)
    const int   wrow = q0 + w * 16;                   // warp's min row
    const int   row0 = wrow + (lane >> 2);
    const int   row1 = row0 + 8;
    const int   nt   = 2 * qi + 2;

    for (int kt = 0; kt < nt; kt++) {
        if (kt > 0) {
            CP_WAIT0();        // tile kt landed (prefetched during kt-1)
            __syncthreads();   // all warps done reading stage (kt+1)&1
        }
        if (kt + 1 < nt) issue_kv(kt + 1, (kt + 1) & 1);

        const int kb = kt * 64;
        if (kb <= wrow + 15) {             // warp has at least one visible key
            const uint32_t KB = S + ATT_KV0 + (kt & 1) * ATT_STAGE;
            const uint32_t KH = KB, KL = KB + 8192;
            const uint32_t VH = KB + 16384, VL = KB + 24576;

            // ---- S = Q . K^T (bf16x3), interleaved issue ----
            float s[8][4];
            #pragma unroll
            for (int nf = 0; nf < 8; nf++)
                #pragma unroll
                for (int r = 0; r < 4; r++) s[nf][r] = 0.f;

            #pragma unroll
            for (int ks = 0; ks < 4; ks++) {
                #pragma unroll
                for (int kg = 0; kg < 4; kg++) {
                    int row = kg * 16 + (lane & 7) + ((lane >> 4) << 3);
                    int ch  = ks * 2 + ((lane >> 3) & 1);
                    uint32_t off = swoff(row, ch);
                    uint32_t kbh[4], kbl[4];
                    LDSM4(kbh[0], kbh[1], kbh[2], kbh[3], KH + off);
                    LDSM4(kbl[0], kbl[1], kbl[2], kbl[3], KL + off);
                    mma16816(s[2 * kg],     qfh[ks], kbh[0], kbh[1]);
                    mma16816(s[2 * kg + 1], qfh[ks], kbh[2], kbh[3]);
                    mma16816(s[2 * kg],     qfh[ks], kbl[0], kbl[1]);
                    mma16816(s[2 * kg + 1], qfh[ks], kbl[2], kbl[3]);
                    mma16816(s[2 * kg],     qfl[ks], kbh[0], kbh[1]);
                    mma16816(s[2 * kg + 1], qfl[ks], kbh[2], kbh[3]);
                }
            }

            // ---- scale + causal mask (static max: no running rescale) ----
            if (kb + 63 > wrow) {          // tile straddles diagonal for warp
                #pragma unroll
                for (int nf = 0; nf < 8; nf++) {
                    int key = kb + nf * 8 + (lane & 3) * 2;
                    s[nf][0] = (key     <= row0) ? s[nf][0] * k2s : -1e30f;
                    s[nf][1] = (key + 1 <= row0) ? s[nf][1] * k2s : -1e30f;
                    s[nf][2] = (key     <= row1) ? s[nf][2] * k2s : -1e30f;
                    s[nf][3] = (key + 1 <= row1) ? s[nf][3] * k2s : -1e30f;
                }
            } else {
                #pragma unroll
                for (int nf = 0; nf < 8; nf++)
                    #pragma unroll
                    for (int r = 0; r < 4; r++) s[nf][r] *= k2s;
            }

            // ---- p = exp2(logit), row sums ----
            float ls0 = 0.f, ls1 = 0.f;
            #pragma unroll
            for (int nf = 0; nf < 8; nf++) {
                s[nf][0] = fexp2(s[nf][0]);
                s[nf][1] = fexp2(s[nf][1]);
                s[nf][2] = fexp2(s[nf][2]);
                s[nf][3] = fexp2(s[nf][3]);
                ls0 += s[nf][0] + s[nf][1];
                ls1 += s[nf][2] + s[nf][3];
            }
            ls0 += __shfl_xor_sync(0xffffffffu, ls0, 1);
            ls0 += __shfl_xor_sync(0xffffffffu, ls0, 2);
            ls1 += __shfl_xor_sync(0xffffffffu, ls1, 1);
            ls1 += __shfl_xor_sync(0xffffffffu, ls1, 2);
            l_run0 += ls0;
            l_run1 += ls1;

            // ---- acc += P . V (bf16x3), interleaved issue ----
            #pragma unroll
            for (int kc = 0; kc < 4; kc++) {
                uint32_t pah[4], pal[4];
                split_pack(pah[0], pal[0], s[2 * kc][0],     s[2 * kc][1]);
                split_pack(pah[1], pal[1], s[2 * kc][2],     s[2 * kc][3]);
                split_pack(pah[2], pal[2], s[2 * kc + 1][0], s[2 * kc + 1][1]);
                split_pack(pah[3], pal[3], s[2 * kc + 1][2], s[2 * kc + 1][3]);
                #pragma unroll
                for (int np = 0; np < 4; np++) {
                    int row = kc * 16 + (lane & 15);
                    int ch  = np * 2 + (lane >> 4);
                    uint32_t off = swoff(row, ch);
                    uint32_t vbh[4], vbl[4];
                    LDSM4T(vbh[0], vbh[1], vbh[2], vbh[3], VH + off);
                    LDSM4T(vbl[0], vbl[1], vbl[2], vbl[3], VL + off);
                    mma16816(acc[2 * np],     pah, vbh[0], vbh[1]);
                    mma16816(acc[2 * np + 1], pah, vbh[2], vbh[3]);
                    mma16816(acc[2 * np],     pah, vbl[0], vbl[1]);
                    mma16816(acc[2 * np + 1], pah, vbl[2], vbl[3]);
                    mma16816(acc[2 * np],     pal, vbh[0], vbh[1]);
                    mma16816(acc[2 * np + 1], pal, vbh[2], vbh[3]);
                }
            }
        }
    }

    // ---- epilogue: normalize, split hi/lo, store to ath/atl [8192,1024] ----
    const float i0 = 1.0f / l_run0;
    const float i1 = 1.0f / l_run1;
    const int b  = by >> 4;
    const int hh = by & 15;
    const int mr0 = b * NL + row0;
    const int mr1 = b * NL + row1;
    const int col = hh * 64 + (lane & 3) * 2;
    #pragma unroll
    for (int nf = 0; nf < 8; nf++) {
        uint32_t h, lo;
        split_pack(h, lo, acc[nf][0] * i0, acc[nf][1] * i0);
        *(uint32_t*)(ath + (size_t)mr0 * NDIM + col + nf * 8) = h;
        *(uint32_t*)(atl + (size_t)mr0 * NDIM + col + nf * 8) = lo;
        split_pack(h, lo, acc[nf][2] * i1, acc[nf][3] * i1);
        *(uint32_t*)(ath + (size_t)mr1 * NDIM + col + nf * 8) = h;
        *(uint32_t*)(atl + (size_t)mr1 * NDIM + col + nf * 8) = lo;
    }
}

// ---------------------------------------------------------------------------
// kernel_launch
// Inputs: [0]=x f32, [1]=attn_mask i32 (implicit tril, unused),
//         [2]=qkv_w, [3]=qkv_b, [4]=proj_w, [5]=proj_b. Output f32 [8192,1024].
// ---------------------------------------------------------------------------
extern "C" void kernel_launch(void* const* d_in, const int* in_sizes, int n_in,
                              void* d_out, int out_size)
{
    (void)in_sizes; (void)n_in; (void)out_size;
    const float* x      = (const float*)d_in[0];
    const float* qkv_w  = (const float*)d_in[2];
    const float* qkv_b  = (const float*)d_in[3];
    const float* proj_w = (const float*)d_in[4];
    const float* proj_b = (const float*)d_in[5];
    float* out = (float*)d_out;

    __nv_bfloat16 *xh, *xl, *wqh, *wql, *wph, *wpl;
    __nv_bfloat16 *qh, *ql, *kh, *kl, *vh, *vl, *ath, *atl;
    cudaGetSymbolAddress((void**)&xh, g_xh);
    cudaGetSymbolAddress((void**)&xl, g_xl);
    cudaGetSymbolAddress((void**)&wqh, g_wqh);
    cudaGetSymbolAddress((void**)&wql, g_wql);
    cudaGetSymbolAddress((void**)&wph, g_wph);
    cudaGetSymbolAddress((void**)&wpl, g_wpl);
    cudaGetSymbolAddress((void**)&qh, g_qh);
    cudaGetSymbolAddress((void**)&ql, g_ql);
    cudaGetSymbolAddress((void**)&kh, g_kh);
    cudaGetSymbolAddress((void**)&kl, g_kl);
    cudaGetSymbolAddress((void**)&vh, g_vh);
    cudaGetSymbolAddress((void**)&vl, g_vl);
    cudaGetSymbolAddress((void**)&ath, g_ath);
    cudaGetSymbolAddress((void**)&atl, g_atl);

    cudaFuncSetAttribute(gemm_mma<0>,
                         cudaFuncAttributeMaxDynamicSharedMemorySize, GEMM_SMEM);
    cudaFuncSetAttribute(gemm_mma<1>,
                         cudaFuncAttributeMaxDynamicSharedMemorySize, GEMM_SMEM);
    cudaFuncSetAttribute(attn_mma,
                         cudaFuncAttributeMaxDynamicSharedMemorySize, ATT_SMEM);

    // Split inputs to bf16 hi/lo
    int n4x = NM * NDIM / 4;
    cvt_split<<<n4x / 256, 256>>>((const float4*)x, (__nv_bfloat162*)xh,
                                  (__nv_bfloat162*)xl, n4x);
    int n4wq = QKV_N * NDIM / 4;
    cvt_split<<<n4wq / 256, 256>>>((const float4*)qkv_w, (__nv_bfloat162*)wqh,
                                   (__nv_bfloat162*)wql, n4wq);
    int n4wp = NDIM * NDIM / 4;
    cvt_split<<<n4wp / 256, 256>>>((const float4*)proj_w, (__nv_bfloat162*)wph,
                                   (__nv_bfloat162*)wpl, n4wp);

    // QKV projection -> split q/k/v buffers in [B,H,L,64] layout
    gemm_mma<1><<<dim3(QKV_N / 128, NM / 128), 256, GEMM_SMEM>>>(
        xh, xl, wqh, wql, qkv_b, nullptr, QKV_N, NDIM,
        qh, ql, kh, kl, vh, vl);

    // Causal MMA attention (128-row q tiles) -> ath/atl
    attn_mma<<<dim3(NL / 128, NB * NHEADS), 256, ATT_SMEM>>>(
        qh, ql, kh, kl, vh, vl, ath, atl);

    // Output projection -> fp32 out
    gemm_mma<0><<<dim3(NDIM / 128, NM / 128), 256, GEMM_SMEM>>>(
        ath, atl, wph, wpl, proj_b, out, NDIM, NDIM,
        nullptr, nullptr, nullptr, nullptr, nullptr, nullptr);
}